// round 2
// baseline (speedup 1.0000x reference)
#include <cuda_runtime.h>

#define NN   100000
#define EDIM 128

// Persistent device scratch (no allocs allowed in kernel_launch).
__device__ float g_a[EDIM];
__device__ float g_b[EDIM];
__device__ float g_c[EDIM];
__device__ float g_s1[NN];
__device__ float g_s2[NN];
__device__ float g_s3[NN];
__device__ int   g_qmin;

// K0: fold Wo into Wq -> three 128-vectors. Also reset qmin (deterministic per launch).
__global__ void k0_prep(const float* __restrict__ Wq, const float* __restrict__ Wo) {
    int j = threadIdx.x;
    if (j == 0) g_qmin = 0x7fffffff;
    if (j < EDIM) {
        g_a[j] = Wo[j];                 // wo1
        float b = 0.f, c = 0.f;
        #pragma unroll 8
        for (int i = 0; i < EDIM; i++) {
            float w = Wo[EDIM + i];     // wo2[i]
            b += w * Wq[i * 2 * EDIM + j];
            c += w * Wq[i * 2 * EDIM + EDIM + j];
        }
        g_b[j] = b;
        g_c[j] = c;
    }
}

// K1: global min over per-edge max(src, dst). Block-level reduce, 1 atomic/block.
__global__ void k1_qmin(const int* __restrict__ ei, int E) {
    __shared__ int smin[8];
    int local = 0x7fffffff;
    int stride = gridDim.x * blockDim.x;
    for (int e = blockIdx.x * blockDim.x + threadIdx.x; e < E; e += stride) {
        int s = ei[e];
        int d = ei[E + e];
        local = min(local, max(s, d));
    }
    #pragma unroll
    for (int o = 16; o; o >>= 1)
        local = min(local, __shfl_xor_sync(0xffffffffu, local, o));
    int warp = threadIdx.x >> 5;
    if ((threadIdx.x & 31) == 0) smin[warp] = local;
    __syncthreads();
    if (threadIdx.x == 0) {
        int v = smin[0];
        #pragma unroll
        for (int w = 1; w < 8; w++) v = min(v, smin[w]);
        atomicMin(&g_qmin, v);
    }
}

// K2: per-node scalar tables. One warp per node; lane loads float4 (coalesced 512B/row).
__global__ void k2_nodes(const float* __restrict__ z, const float* __restrict__ z0, int N) {
    __shared__ float sa[EDIM], sb[EDIM], sc[EDIM];
    for (int i = threadIdx.x; i < EDIM; i += blockDim.x) {
        sa[i] = g_a[i]; sb[i] = g_b[i]; sc[i] = g_c[i];
    }
    __syncthreads();
    int warp = threadIdx.x >> 5;
    int lane = threadIdx.x & 31;
    int node = blockIdx.x * (blockDim.x >> 5) + warp;
    if (node >= N) return;

    const float4 v = ((const float4*)(z  + (size_t)node * EDIM))[lane];
    const float4 w = ((const float4*)(z0 + (size_t)node * EDIM))[lane];
    int k = lane * 4;
    float s1 = v.x * sa[k] + v.y * sa[k + 1] + v.z * sa[k + 2] + v.w * sa[k + 3];
    float s2 = v.x * sb[k] + v.y * sb[k + 1] + v.z * sb[k + 2] + v.w * sb[k + 3];
    float s3 = w.x * sc[k] + w.y * sc[k + 1] + w.z * sc[k + 2] + w.w * sc[k + 3];
    #pragma unroll
    for (int o = 16; o; o >>= 1) {
        s1 += __shfl_xor_sync(0xffffffffu, s1, o);
        s2 += __shfl_xor_sync(0xffffffffu, s2, o);
        s3 += __shfl_xor_sync(0xffffffffu, s3, o);
    }
    if (lane == 0) {
        g_s1[node] = s1;
        g_s2[node] = s2;
        g_s3[node] = s3;
    }
}

// K3: per-edge output = s1[src] + s2[dst] + s3[max(src,dst)-qmin] + bo.
__global__ void k3_edges(const int* __restrict__ ei, const float* __restrict__ bo,
                         float* __restrict__ out, int E) {
    int e = blockIdx.x * blockDim.x + threadIdx.x;
    if (e >= E) return;
    int qmin = g_qmin;
    float bias = bo[0];
    int s = ei[e];
    int d = ei[E + e];
    int q = max(s, d) - qmin;
    out[e] = g_s1[s] + g_s2[d] + g_s3[q] + bias;
}

extern "C" void kernel_launch(void* const* d_in, const int* in_sizes, int n_in,
                              void* d_out, int out_size) {
    // Inputs (metadata order): z, edge_index, z0, Wq, Wo, bo
    const float* z  = (const float*)d_in[0];
    const int*   ei = (const int*)d_in[1];      // jax int64 -> int32 (x64 disabled)
    const float* z0 = (const float*)d_in[2];
    const float* Wq = (const float*)d_in[3];
    const float* Wo = (const float*)d_in[4];
    const float* bo = (const float*)d_in[5];
    float* out = (float*)d_out;

    int N = in_sizes[0] / EDIM;     // 100000
    int E = in_sizes[1] / 2;        // 1000000

    k0_prep<<<1, 128>>>(Wq, Wo);
    k1_qmin<<<592, 256>>>(ei, E);                       // grid-stride, ~4 blocks/SM
    k2_nodes<<<(N + 7) / 8, 256>>>(z, z0, N);           // 1 warp/node
    k3_edges<<<(E + 255) / 256, 256>>>(ei, bo, out, E);
}

// round 3
// speedup vs baseline: 1.4114x; 1.4114x over previous
#include <cuda_runtime.h>

#define NN    100000
#define EDIM  128
#define QBLKS 284          // qmin partial blocks inside k0
#define K0PREP 16          // prep blocks inside k0 (16 blocks * 8 warps = 128 j's)

// Persistent device scratch (no allocs in kernel_launch).
__device__ float  g_a[EDIM];
__device__ float  g_b[EDIM];
__device__ float  g_c[EDIM];
__device__ float2 g_T1[NN];     // (s1, s1 + s3shift)
__device__ float2 g_T2[NN];     // (s2 + bias, s2 + s3shift + bias)
__device__ int    g_partmin[QBLKS];
__device__ int    g_qmin;

// ───────────────────────────── K0: prep (blocks 0..15) + qmin partials (16..299)
__global__ void k0_prep_qmin(const float* __restrict__ Wq, const float* __restrict__ Wo,
                             const int* __restrict__ ei, int E) {
    int bid = blockIdx.x;
    int warp = threadIdx.x >> 5;
    int lane = threadIdx.x & 31;

    if (bid < K0PREP) {
        // One warp per output column j; lanes split the 128-term reduction.
        int j = bid * 8 + warp;
        float b = 0.f, c = 0.f;
        #pragma unroll
        for (int k = 0; k < 4; k++) {
            int i = lane + 32 * k;
            float w = Wo[EDIM + i];
            b += w * Wq[i * 2 * EDIM + j];
            c += w * Wq[i * 2 * EDIM + EDIM + j];
        }
        #pragma unroll
        for (int o = 16; o; o >>= 1) {
            b += __shfl_xor_sync(0xffffffffu, b, o);
            c += __shfl_xor_sync(0xffffffffu, c, o);
        }
        if (lane == 0) {
            g_a[j] = Wo[j];
            g_b[j] = b;
            g_c[j] = c;
        }
    } else {
        // qmin partial: grid-stride over edges, one plain store per block (no reset needed).
        __shared__ int smin[8];
        int pb = bid - K0PREP;
        int local = 0x7fffffff;
        int stride = QBLKS * 256;
        for (int e = pb * 256 + threadIdx.x; e < E; e += stride) {
            int s = ei[e];
            int d = ei[E + e];
            local = min(local, max(s, d));
        }
        #pragma unroll
        for (int o = 16; o; o >>= 1)
            local = min(local, __shfl_xor_sync(0xffffffffu, local, o));
        if (lane == 0) smin[warp] = local;
        __syncthreads();
        if (threadIdx.x == 0) {
            int v = smin[0];
            #pragma unroll
            for (int w = 1; w < 8; w++) v = min(v, smin[w]);
            g_partmin[pb] = v;
        }
    }
}

// ───────────────────────────── K1b: reduce partials -> g_qmin (1 block)
__global__ void k1b_qmin_final() {
    __shared__ int smin[16];
    int t = threadIdx.x;                       // 512 threads
    int local = (t < QBLKS) ? g_partmin[t] : 0x7fffffff;
    #pragma unroll
    for (int o = 16; o; o >>= 1)
        local = min(local, __shfl_xor_sync(0xffffffffu, local, o));
    if ((t & 31) == 0) smin[t >> 5] = local;
    __syncthreads();
    if (t == 0) {
        int v = smin[0];
        #pragma unroll
        for (int w = 1; w < 16; w++) v = min(v, smin[w]);
        g_qmin = v;
    }
}

// ───────────────────────────── K2: per-node tables (one warp per node)
__global__ void k2_nodes(const float* __restrict__ z, const float* __restrict__ z0,
                         const float* __restrict__ bo, int N) {
    __shared__ float sa[EDIM], sb[EDIM], sc[EDIM];
    for (int i = threadIdx.x; i < EDIM; i += blockDim.x) {
        sa[i] = g_a[i]; sb[i] = g_b[i]; sc[i] = g_c[i];
    }
    __syncthreads();
    int warp = threadIdx.x >> 5;
    int lane = threadIdx.x & 31;
    int node = blockIdx.x * (blockDim.x >> 5) + warp;
    if (node >= N) return;

    int   qmin = g_qmin;
    float bias = bo[0];

    const float4 v = ((const float4*)(z + (size_t)node * EDIM))[lane];
    int k = lane * 4;
    float s1 = v.x * sa[k] + v.y * sa[k + 1] + v.z * sa[k + 2] + v.w * sa[k + 3];
    float s2 = v.x * sb[k] + v.y * sb[k + 1] + v.z * sb[k + 2] + v.w * sb[k + 3];

    float s3 = 0.f;
    int m = node - qmin;                       // shifted z0 row feeding A/B at this node
    if (m >= 0) {
        const float4 w = ((const float4*)(z0 + (size_t)m * EDIM))[lane];
        s3 = w.x * sc[k] + w.y * sc[k + 1] + w.z * sc[k + 2] + w.w * sc[k + 3];
    }
    #pragma unroll
    for (int o = 16; o; o >>= 1) {
        s1 += __shfl_xor_sync(0xffffffffu, s1, o);
        s2 += __shfl_xor_sync(0xffffffffu, s2, o);
        s3 += __shfl_xor_sync(0xffffffffu, s3, o);
    }
    if (lane == 0) {
        g_T1[node] = make_float2(s1, s1 + s3);
        g_T2[node] = make_float2(s2 + bias, s2 + s3 + bias);
    }
}

// ───────────────────────────── K3: per-edge output, 4 edges/thread, 2 gathers/edge
__global__ void k3_edges(const int* __restrict__ ei, float* __restrict__ out, int E) {
    int base = (blockIdx.x * blockDim.x + threadIdx.x) * 4;
    if (base + 3 < E) {
        int4 s4 = *(const int4*)(ei + base);
        int4 d4 = *(const int4*)(ei + E + base);
        float2 u0 = g_T1[s4.x], u1 = g_T1[s4.y], u2 = g_T1[s4.z], u3 = g_T1[s4.w];
        float2 v0 = g_T2[d4.x], v1 = g_T2[d4.y], v2 = g_T2[d4.z], v3 = g_T2[d4.w];
        float4 r;
        r.x = (s4.x >= d4.x) ? (u0.y + v0.x) : (u0.x + v0.y);
        r.y = (s4.y >= d4.y) ? (u1.y + v1.x) : (u1.x + v1.y);
        r.z = (s4.z >= d4.z) ? (u2.y + v2.x) : (u2.x + v2.y);
        r.w = (s4.w >= d4.w) ? (u3.y + v3.x) : (u3.x + v3.y);
        *(float4*)(out + base) = r;
    } else {
        for (int e = base; e < E; e++) {
            int s = ei[e], d = ei[E + e];
            float2 u = g_T1[s];
            float2 v = g_T2[d];
            out[e] = (s >= d) ? (u.y + v.x) : (u.x + v.y);
        }
    }
}

extern "C" void kernel_launch(void* const* d_in, const int* in_sizes, int n_in,
                              void* d_out, int out_size) {
    // Inputs (metadata order): z, edge_index, z0, Wq, Wo, bo
    const float* z  = (const float*)d_in[0];
    const int*   ei = (const int*)d_in[1];      // jax default int32
    const float* z0 = (const float*)d_in[2];
    const float* Wq = (const float*)d_in[3];
    const float* Wo = (const float*)d_in[4];
    const float* bo = (const float*)d_in[5];
    float* out = (float*)d_out;

    int N = in_sizes[0] / EDIM;     // 100000
    int E = in_sizes[1] / 2;        // 1000000

    k0_prep_qmin<<<K0PREP + QBLKS, 256>>>(Wq, Wo, ei, E);
    k1b_qmin_final<<<1, 512>>>();
    k2_nodes<<<(N + 7) / 8, 256>>>(z, z0, bo, N);
    int threads3 = (E + 3) / 4;
    k3_edges<<<(threads3 + 255) / 256, 256>>>(ei, out, E);
}

// round 4
// speedup vs baseline: 1.4652x; 1.0381x over previous
#include <cuda_runtime.h>

#define NN     100000
#define EDIM   128
#define QBLKS  288          // qmin partial blocks inside k0
#define K0PREP 16           // prep blocks (16 blocks * 8 warps = 128 j's)

// Persistent device scratch (no allocs in kernel_launch).
__device__ float  g_a[EDIM];
__device__ float  g_b[EDIM];
__device__ float  g_c[EDIM];
__device__ float2 g_T1[NN];                 // (s1, s1 + s3shift)
__device__ float2 g_T2[NN];                 // (s2 + bias, s2 + s3shift + bias)
__device__ int    g_qmin = 0x7fffffff;      // reset by k3 tail each run

// ───────────── K0: blocks 0..15 fold Wo into Wq; blocks 16.. compute qmin partials
__global__ void k0_prep_qmin(const float* __restrict__ Wq, const float* __restrict__ Wo,
                             const int* __restrict__ ei, int E) {
    int bid  = blockIdx.x;
    int warp = threadIdx.x >> 5;
    int lane = threadIdx.x & 31;

    if (bid < K0PREP) {
        int j = bid * 8 + warp;             // output column
        float b = 0.f, c = 0.f;
        #pragma unroll
        for (int k = 0; k < 4; k++) {
            int i = lane + 32 * k;
            float w = Wo[EDIM + i];
            b += w * Wq[i * 2 * EDIM + j];
            c += w * Wq[i * 2 * EDIM + EDIM + j];
        }
        #pragma unroll
        for (int o = 16; o; o >>= 1) {
            b += __shfl_xor_sync(0xffffffffu, b, o);
            c += __shfl_xor_sync(0xffffffffu, c, o);
        }
        if (lane == 0) {
            g_a[j] = Wo[j];
            g_b[j] = b;
            g_c[j] = c;
        }
    } else {
        __shared__ int smin[8];
        int pb = bid - K0PREP;
        int local = 0x7fffffff;
        int stride = QBLKS * 256;
        for (int e = pb * 256 + threadIdx.x; e < E; e += stride) {
            int s = ei[e];
            int d = ei[E + e];
            local = min(local, max(s, d));
        }
        #pragma unroll
        for (int o = 16; o; o >>= 1)
            local = min(local, __shfl_xor_sync(0xffffffffu, local, o));
        if (lane == 0) smin[warp] = local;
        __syncthreads();
        if (threadIdx.x == 0) {
            int v = smin[0];
            #pragma unroll
            for (int w = 1; w < 8; w++) v = min(v, smin[w]);
            atomicMin(&g_qmin, v);
        }
    }
}

// ───────────── K2: node tables, 4 nodes per warp (8 LDG.128 in flight per warp)
__global__ void k2_nodes(const float* __restrict__ z, const float* __restrict__ z0,
                         const float* __restrict__ bo, int N) {
    __shared__ float sa[EDIM], sb[EDIM], sc[EDIM];
    for (int i = threadIdx.x; i < EDIM; i += blockDim.x) {
        sa[i] = g_a[i]; sb[i] = g_b[i]; sc[i] = g_c[i];
    }
    __syncthreads();
    int warp  = threadIdx.x >> 5;
    int lane  = threadIdx.x & 31;
    int node0 = (blockIdx.x * (blockDim.x >> 5) + warp) * 4;
    if (node0 >= N) return;

    int   qmin = g_qmin;
    float bias = bo[0];
    int   k    = lane * 4;

    float4 vz[4], w4[4];
    bool   hasw[4];
    #pragma unroll
    for (int t = 0; t < 4; t++) {
        int node = node0 + t;
        int nc   = (node < N) ? node : (N - 1);          // clamp (redundant work, no branch div)
        vz[t] = ((const float4*)(z + (size_t)nc * EDIM))[lane];
        int m = nc - qmin;
        hasw[t] = (m >= 0);
        int mc = hasw[t] ? m : 0;
        w4[t] = ((const float4*)(z0 + (size_t)mc * EDIM))[lane];
    }
    #pragma unroll
    for (int t = 0; t < 4; t++) {
        int node = node0 + t;
        float s1 = vz[t].x * sa[k] + vz[t].y * sa[k+1] + vz[t].z * sa[k+2] + vz[t].w * sa[k+3];
        float s2 = vz[t].x * sb[k] + vz[t].y * sb[k+1] + vz[t].z * sb[k+2] + vz[t].w * sb[k+3];
        float s3 = hasw[t]
                 ? (w4[t].x * sc[k] + w4[t].y * sc[k+1] + w4[t].z * sc[k+2] + w4[t].w * sc[k+3])
                 : 0.f;
        #pragma unroll
        for (int o = 16; o; o >>= 1) {
            s1 += __shfl_xor_sync(0xffffffffu, s1, o);
            s2 += __shfl_xor_sync(0xffffffffu, s2, o);
            s3 += __shfl_xor_sync(0xffffffffu, s3, o);
        }
        if (lane == 0 && node < N) {
            g_T1[node] = make_float2(s1, s1 + s3);
            g_T2[node] = make_float2(s2 + bias, s2 + s3 + bias);
        }
    }
}

// ───────────── K3: per-edge output, 8 edges/thread (16 gathers in flight)
__global__ void k3_edges(const int* __restrict__ ei, float* __restrict__ out, int E) {
    // reset qmin for next graph replay (k2 already consumed it this run)
    if (blockIdx.x == 0 && threadIdx.x == 0) g_qmin = 0x7fffffff;

    int base = (blockIdx.x * blockDim.x + threadIdx.x) * 8;
    if (base + 7 < E) {
        int4 sA = *(const int4*)(ei + base);
        int4 sB = *(const int4*)(ei + base + 4);
        int4 dA = *(const int4*)(ei + E + base);
        int4 dB = *(const int4*)(ei + E + base + 4);
        int s[8] = { sA.x, sA.y, sA.z, sA.w, sB.x, sB.y, sB.z, sB.w };
        int d[8] = { dA.x, dA.y, dA.z, dA.w, dB.x, dB.y, dB.z, dB.w };
        float2 u[8], v[8];
        #pragma unroll
        for (int t = 0; t < 8; t++) u[t] = g_T1[s[t]];
        #pragma unroll
        for (int t = 0; t < 8; t++) v[t] = g_T2[d[t]];
        float r[8];
        #pragma unroll
        for (int t = 0; t < 8; t++)
            r[t] = (s[t] >= d[t]) ? (u[t].y + v[t].x) : (u[t].x + v[t].y);
        *(float4*)(out + base)     = make_float4(r[0], r[1], r[2], r[3]);
        *(float4*)(out + base + 4) = make_float4(r[4], r[5], r[6], r[7]);
    } else {
        for (int e = base; e < E; e++) {
            int ss = ei[e], dd = ei[E + e];
            float2 u = g_T1[ss];
            float2 v = g_T2[dd];
            out[e] = (ss >= dd) ? (u.y + v.x) : (u.x + v.y);
        }
    }
}

extern "C" void kernel_launch(void* const* d_in, const int* in_sizes, int n_in,
                              void* d_out, int out_size) {
    // Inputs (metadata order): z, edge_index, z0, Wq, Wo, bo
    const float* z  = (const float*)d_in[0];
    const int*   ei = (const int*)d_in[1];      // jax default int32
    const float* z0 = (const float*)d_in[2];
    const float* Wq = (const float*)d_in[3];
    const float* Wo = (const float*)d_in[4];
    const float* bo = (const float*)d_in[5];
    float* out = (float*)d_out;

    int N = in_sizes[0] / EDIM;     // 100000
    int E = in_sizes[1] / 2;        // 1000000

    k0_prep_qmin<<<K0PREP + QBLKS, 256>>>(Wq, Wo, ei, E);
    // nodes: 4 per warp, 8 warps per block -> 32 nodes/block
    k2_nodes<<<(N + 31) / 32, 256>>>(z, z0, bo, N);
    int threads3 = (E + 7) / 8;
    k3_edges<<<(threads3 + 255) / 256, 256>>>(ei, out, E);
}

// round 5
// speedup vs baseline: 1.4687x; 1.0024x over previous
#include <cuda_runtime.h>

#define NN     100000
#define EDIM   128
#define QBLKS  1168         // qmin partial blocks inside k0 (int4 sweep)
#define K0PREP 16           // prep blocks (16 blocks * 8 warps = 128 j's)

// Persistent device scratch (no allocs in kernel_launch).
__device__ float  g_a[EDIM];
__device__ float  g_b[EDIM];
__device__ float  g_c[EDIM];
__device__ float2 g_T1[NN];                 // (s1, s1 + s3shift)
__device__ float2 g_T2[NN];                 // (s2 + bias, s2 + s3shift + bias)
__device__ int    g_qmin = 0x7fffffff;      // reset by k3 each run

// ───────────── K0: blocks 0..15 fold Wo into Wq; blocks 16.. qmin partials (int4)
__global__ void k0_prep_qmin(const float* __restrict__ Wq, const float* __restrict__ Wo,
                             const int* __restrict__ ei, int E) {
    int bid  = blockIdx.x;
    int warp = threadIdx.x >> 5;
    int lane = threadIdx.x & 31;

    if (bid < K0PREP) {
        int j = bid * 8 + warp;             // output column
        float b = 0.f, c = 0.f;
        #pragma unroll
        for (int k = 0; k < 4; k++) {
            int i = lane + 32 * k;
            float w = Wo[EDIM + i];
            b += w * Wq[i * 2 * EDIM + j];
            c += w * Wq[i * 2 * EDIM + EDIM + j];
        }
        #pragma unroll
        for (int o = 16; o; o >>= 1) {
            b += __shfl_xor_sync(0xffffffffu, b, o);
            c += __shfl_xor_sync(0xffffffffu, c, o);
        }
        if (lane == 0) {
            g_a[j] = Wo[j];
            g_b[j] = b;
            g_c[j] = c;
        }
    } else {
        // int4 sweep: 4 edges per iteration per thread, ~1 iteration/thread at this grid.
        __shared__ int smin[8];
        int pb = bid - K0PREP;
        int E4 = E >> 2;                                    // E divisible by 4
        const int4* s4p = (const int4*)ei;
        const int4* d4p = (const int4*)(ei + E);
        int local = 0x7fffffff;
        int stride = QBLKS * 256;
        for (int i = pb * 256 + threadIdx.x; i < E4; i += stride) {
            int4 s = s4p[i];
            int4 d = d4p[i];
            int m0 = max(s.x, d.x), m1 = max(s.y, d.y);
            int m2 = max(s.z, d.z), m3 = max(s.w, d.w);
            local = min(local, min(min(m0, m1), min(m2, m3)));
        }
        // tail (E not multiple of 4)
        for (int e = (E4 << 2) + pb * 256 + threadIdx.x; e < E; e += stride)
            local = min(local, max(ei[e], ei[E + e]));
        #pragma unroll
        for (int o = 16; o; o >>= 1)
            local = min(local, __shfl_xor_sync(0xffffffffu, local, o));
        if (lane == 0) smin[warp] = local;
        __syncthreads();
        if (threadIdx.x == 0) {
            int v = smin[0];
            #pragma unroll
            for (int w = 1; w < 8; w++) v = min(v, smin[w]);
            atomicMin(&g_qmin, v);
        }
    }
}

// ───────────── K2: node tables, 4 nodes per warp (8 LDG.128 in flight per warp)
__global__ void k2_nodes(const float* __restrict__ z, const float* __restrict__ z0,
                         const float* __restrict__ bo, int N) {
    __shared__ float sa[EDIM], sb[EDIM], sc[EDIM];
    for (int i = threadIdx.x; i < EDIM; i += blockDim.x) {
        sa[i] = g_a[i]; sb[i] = g_b[i]; sc[i] = g_c[i];
    }
    __syncthreads();
    int warp  = threadIdx.x >> 5;
    int lane  = threadIdx.x & 31;
    int node0 = (blockIdx.x * (blockDim.x >> 5) + warp) * 4;
    if (node0 >= N) return;

    int   qmin = g_qmin;
    float bias = bo[0];
    int   k    = lane * 4;

    float4 vz[4], w4[4];
    bool   hasw[4];
    #pragma unroll
    for (int t = 0; t < 4; t++) {
        int node = node0 + t;
        int nc   = (node < N) ? node : (N - 1);
        vz[t] = ((const float4*)(z + (size_t)nc * EDIM))[lane];
        int m = nc - qmin;
        hasw[t] = (m >= 0);
        int mc = hasw[t] ? m : 0;
        w4[t] = ((const float4*)(z0 + (size_t)mc * EDIM))[lane];
    }
    #pragma unroll
    for (int t = 0; t < 4; t++) {
        int node = node0 + t;
        float s1 = vz[t].x * sa[k] + vz[t].y * sa[k+1] + vz[t].z * sa[k+2] + vz[t].w * sa[k+3];
        float s2 = vz[t].x * sb[k] + vz[t].y * sb[k+1] + vz[t].z * sb[k+2] + vz[t].w * sb[k+3];
        float s3 = hasw[t]
                 ? (w4[t].x * sc[k] + w4[t].y * sc[k+1] + w4[t].z * sc[k+2] + w4[t].w * sc[k+3])
                 : 0.f;
        #pragma unroll
        for (int o = 16; o; o >>= 1) {
            s1 += __shfl_xor_sync(0xffffffffu, s1, o);
            s2 += __shfl_xor_sync(0xffffffffu, s2, o);
            s3 += __shfl_xor_sync(0xffffffffu, s3, o);
        }
        if (lane == 0 && node < N) {
            g_T1[node] = make_float2(s1, s1 + s3);
            g_T2[node] = make_float2(s2 + bias, s2 + s3 + bias);
        }
    }
}

// ───────────── K3: per-edge output, 8 edges/thread (16 gathers in flight)
__global__ void k3_edges(const int* __restrict__ ei, float* __restrict__ out, int E) {
    // reset qmin for next graph replay (consumed by k2 this run; k3 doesn't read it)
    if (blockIdx.x == 0 && threadIdx.x == 0) g_qmin = 0x7fffffff;

    int base = (blockIdx.x * blockDim.x + threadIdx.x) * 8;
    if (base + 7 < E) {
        int4 sA = *(const int4*)(ei + base);
        int4 sB = *(const int4*)(ei + base + 4);
        int4 dA = *(const int4*)(ei + E + base);
        int4 dB = *(const int4*)(ei + E + base + 4);
        int s[8] = { sA.x, sA.y, sA.z, sA.w, sB.x, sB.y, sB.z, sB.w };
        int d[8] = { dA.x, dA.y, dA.z, dA.w, dB.x, dB.y, dB.z, dB.w };
        float2 u[8], v[8];
        #pragma unroll
        for (int t = 0; t < 8; t++) u[t] = g_T1[s[t]];
        #pragma unroll
        for (int t = 0; t < 8; t++) v[t] = g_T2[d[t]];
        float r[8];
        #pragma unroll
        for (int t = 0; t < 8; t++)
            r[t] = (s[t] >= d[t]) ? (u[t].y + v[t].x) : (u[t].x + v[t].y);
        *(float4*)(out + base)     = make_float4(r[0], r[1], r[2], r[3]);
        *(float4*)(out + base + 4) = make_float4(r[4], r[5], r[6], r[7]);
    } else {
        for (int e = base; e < E; e++) {
            int ss = ei[e], dd = ei[E + e];
            float2 u = g_T1[ss];
            float2 v = g_T2[dd];
            out[e] = (ss >= dd) ? (u.y + v.x) : (u.x + v.y);
        }
    }
}

extern "C" void kernel_launch(void* const* d_in, const int* in_sizes, int n_in,
                              void* d_out, int out_size) {
    // Inputs (metadata order): z, edge_index, z0, Wq, Wo, bo
    const float* z  = (const float*)d_in[0];
    const int*   ei = (const int*)d_in[1];      // jax default int32
    const float* z0 = (const float*)d_in[2];
    const float* Wq = (const float*)d_in[3];
    const float* Wo = (const float*)d_in[4];
    const float* bo = (const float*)d_in[5];
    float* out = (float*)d_out;

    int N = in_sizes[0] / EDIM;     // 100000
    int E = in_sizes[1] / 2;        // 1000000

    k0_prep_qmin<<<K0PREP + QBLKS, 256>>>(Wq, Wo, ei, E);
    k2_nodes<<<(N + 31) / 32, 256>>>(z, z0, bo, N);
    int threads3 = (E + 7) / 8;
    k3_edges<<<(threads3 + 255) / 256, 256>>>(ei, out, E);
}